// round 14
// baseline (speedup 1.0000x reference)
#include <cuda_runtime.h>
#include <cstdint>
#include <math.h>

// ===================== problem constants =====================
#define DDIM    256
#define KDICT   1024
#define M_CTA   64
#define N_CHUNK 32
#define N_STAGE 16              // chunks per team (2 teams * 16 * 32 = 1024)
#define NKS     16              // k16 steps over DDIM
#define QSCALE  32.0f
#define QINV2   (-2.0f / (QSCALE * QSCALE))   // -2/1024

// ===================== smem layout (bytes) =====================
#define OFF_A     0
#define A_BYTES   (M_CTA*DDIM)                   // 16384 int8 frag layout
#define OFF_CN    (OFF_A + A_BYTES)              // 16384 : 1024 f32 norms
#define OFF_T3D   (OFF_CN + KDICT*4)             // 20480 : [2][64][3] f32
#define OFF_T3I   (OFF_T3D + 2*64*3*4)           // 22016 : [2][64][3] i32
#define OFF_IDX   (OFF_T3I + 2*64*3*4)           // 23552 : [64] i32
#define SMEM_BYTES (OFF_IDX + 256)               // 23808

// ===================== device scratch (no allocs allowed) =====================
__device__ __align__(16) float    g_cnorm_f[KDICT];
__device__ __align__(16) double   g_cnorm_d[KDICT];
// int8 codebook, packed u32, PER-COL PAIRED WORD ORDER:
// word j' = kq*8 + ctg*2 + kh   (from original j = kq*8 + kh*4 + ctg)
__device__ __align__(16) uint32_t g_cb_i8[KDICT * DDIM / 4];
__device__ float g_loss_sum;
__device__ float g_counts[KDICT];

// ===================== helpers =====================
__device__ __forceinline__ uint32_t smem_to_u32(const void* p) {
    uint32_t a;
    asm("{ .reg .u64 t; cvta.to.shared.u64 t, %1; cvt.u32.u64 %0, t; }" : "=r"(a) : "l"(p));
    return a;
}

__device__ __forceinline__ uint32_t quant4(float4 v) {
    int a = __float2int_rn(fminf(fmaxf(v.x * QSCALE, -127.f), 127.f));
    int b = __float2int_rn(fminf(fmaxf(v.y * QSCALE, -127.f), 127.f));
    int c = __float2int_rn(fminf(fmaxf(v.z * QSCALE, -127.f), 127.f));
    int d = __float2int_rn(fminf(fmaxf(v.w * QSCALE, -127.f), 127.f));
    return (uint32_t)(a & 255) | ((uint32_t)(b & 255) << 8)
         | ((uint32_t)(c & 255) << 16) | ((uint32_t)(d & 255) << 24);
}

// m16n8k16 s8: a0 = row g (k=ctg*4..+3), a1 = row g+8. b0 = col g, k = ctg*4..+3.
// c0/c1 = row g cols ctg*2/+1; c2/c3 = row g+8.   (R6-validated)
__device__ __forceinline__ void mma_s8_k16(int d[4], uint32_t a0, uint32_t a1, uint32_t b0) {
    asm volatile(
        "mma.sync.aligned.m16n8k16.row.col.s32.s8.s8.s32 "
        "{%0,%1,%2,%3}, {%4,%5}, {%6}, {%0,%1,%2,%3};"
        : "+r"(d[0]), "+r"(d[1]), "+r"(d[2]), "+r"(d[3])
        : "r"(a0), "r"(a1), "r"(b0));
}

// LDG.64 from L2 (read-only path), compile-time byte offset folded in.
#define LDG2(b0, b1, ptr, imm) \
    asm volatile("ld.global.nc.v2.u32 {%0,%1}, [%2+" #imm "];" \
        : "=r"(b0), "=r"(b1) : "l"(ptr))

__device__ __forceinline__ void t3ins(float d[3], int idx[3], float nd, int ni) {
    if (nd < d[2]) {
        if (nd < d[1]) {
            d[2] = d[1]; idx[2] = idx[1];
            if (nd < d[0]) { d[1] = d[0]; idx[1] = idx[0]; d[0] = nd; idx[0] = ni; }
            else           { d[1] = nd;  idx[1] = ni; }
        } else { d[2] = nd; idx[2] = ni; }
    }
}

// ===================== K0: codebook norms + permuted int8 codebook + zero accumulators =====================
__global__ void vq_prep(const float* __restrict__ cb) {
    int tid = threadIdx.x;
    if (blockIdx.x == 0) {
        if (tid == 0) g_loss_sum = 0.f;
        for (int i = tid; i < KDICT; i += 256) g_counts[i] = 0.f;
    }
    int row  = blockIdx.x * 8 + (tid >> 5);   // 128 blocks * 8 warps = 1024 rows
    int lane = tid & 31;
    const float4* r4 = (const float4*)(cb + (size_t)row * DDIM);
    double s = 0.0;
    #pragma unroll
    for (int j = lane; j < 64; j += 32) {
        float4 v = r4[j];
        s += (double)v.x * v.x + (double)v.y * v.y + (double)v.z * v.z + (double)v.w * v.w;
        // paired word order: j = kq*8 + kh*4 + ctg  ->  j' = kq*8 + ctg*2 + kh
        int jp = (j & 0x38) | ((j & 3) << 1) | ((j >> 2) & 1);
        g_cb_i8[row * 64 + jp] = quant4(v);
    }
    #pragma unroll
    for (int o = 16; o > 0; o >>= 1) s += __shfl_down_sync(0xffffffffu, s, o);
    if (lane == 0) { g_cnorm_d[row] = s; g_cnorm_f[row] = (float)s; }
}

// ===================== K1: int8 IMMA GEMM (B from L2) + top-3 argmin + rerank + gather =====================
__global__ __launch_bounds__(256, 4)
void vq_main(const float* __restrict__ z, const float* __restrict__ cb,
             float* __restrict__ out) {
    extern __shared__ char smem[];
    const uint32_t sb  = smem_to_u32(smem);
    const int tid  = threadIdx.x;
    const int team = tid >> 7;          // 0 or 1 (chunk partition only; no shared B)
    const int wm   = (tid >> 5) & 3;    // warp m16-block within team
    const int lane = tid & 31;
    const int g    = lane >> 2;
    const int ctg  = lane & 3;
    const size_t rowBase = (size_t)blockIdx.x * M_CTA;

    // ---- codebook norms -> smem (256 thr x float4 = 1024 floats)
    {
        const float4* cf4 = (const float4*)g_cnorm_f;
        *((float4*)(smem + OFF_CN) + tid) = cf4[tid];
    }

    // ---- prologue: A tile 64x256 fp32 -> int8, m16n8k16 fragment layout.
    // Block per (mw 0..3, kq 0..7): 512 bytes holding BOTH k16 steps (kh 0/1):
    //   word = (mw*8+kq)*128 + (lane' ^ ((kq&7)<<2))*4 + (kh*2 + rowhalf)
    {
        const float4* z4 = (const float4*)z + rowBase * (DDIM / 4);
        uint32_t* A = (uint32_t*)(smem + OFF_A);
        #pragma unroll 4
        for (int it = 0; it < 16; it++) {
            int i4 = tid + it * 256;            // 0..4095
            int r  = i4 >> 6;                   // row 0..63
            int k0 = (i4 & 63) << 2;            // k 0..252, mult of 4
            uint32_t pack = quant4(z4[i4]);
            int mw = r >> 4, rho = r & 15;
            int gg = rho & 7, rh = rho >> 3;
            int ks = k0 >> 4, tg = (k0 & 15) >> 2;
            int kq = ks >> 1, kh = ks & 1;
            int lanep = (gg * 4 + tg) ^ ((kq & 7) << 2);
            int word  = (mw * 8 + kq) * 128 + lanep * 4 + (kh * 2 + rh);
            A[word] = pack;
        }
    }
    __syncthreads();

    // ---- running per-thread top-3 for 2 row-slots (rows g, g+8 of block wm)
    float t3d[2][3]; int t3i[2][3];
    #pragma unroll
    for (int rw = 0; rw < 2; rw++)
        #pragma unroll
        for (int s = 0; s < 3; s++) { t3d[rw][s] = 3.4e38f; t3i[rw][s] = 0; }

    const float* scn = (const float*)(smem + OFF_CN);
    const uint32_t aBase = sb + OFF_A + (uint32_t)(wm << 12);   // wm*4096
    // per-lane B base within a chunk: col (n0 + g), words ctg*2
    const char* bLane = (const char*)g_cb_i8 + (uint32_t)(g << 8) + (uint32_t)(ctg << 3);

    for (int stage = 0; stage < N_STAGE; stage++) {
        const int chunk = stage * 2 + team;
        const int n0 = chunk * N_CHUNK;
        const char* bp = bLane + (size_t)n0 * 256;   // + nt*2048 + kq*32 immediates

        int acc[4][4];
        #pragma unroll
        for (int nt = 0; nt < 4; nt++)
            #pragma unroll
            for (int e = 0; e < 4; e++) acc[nt][e] = 0;

        // 1-deep pipeline: prefetch b(kq+1) while issuing MMAs(kq)
        uint32_t bc[8], bn[8];
        LDG2(bc[0], bc[1], bp, 0);
        LDG2(bc[2], bc[3], bp, 2048);
        LDG2(bc[4], bc[5], bp, 4096);
        LDG2(bc[6], bc[7], bp, 6144);

        #pragma unroll
        for (int kq = 0; kq < NKS / 2; kq++) {
            uint32_t a[4];
            uint32_t aAddr = aBase + (uint32_t)(kq << 9)
                           + (uint32_t)((lane ^ ((kq & 7) << 2)) << 4);
            asm volatile("ld.shared.v4.b32 {%0,%1,%2,%3}, [%4];"
                : "=r"(a[0]), "=r"(a[1]), "=r"(a[2]), "=r"(a[3]) : "r"(aAddr));
            if (kq < NKS / 2 - 1) {
                const char* bq = bp + (kq + 1) * 32;
                LDG2(bn[0], bn[1], bq, 0);
                LDG2(bn[2], bn[3], bq, 2048);
                LDG2(bn[4], bn[5], bq, 4096);
                LDG2(bn[6], bn[7], bq, 6144);
            }
            #pragma unroll
            for (int nt = 0; nt < 4; nt++) {
                mma_s8_k16(acc[nt], a[0], a[1], bc[2*nt]);     // ks0: rows wm*16 + {g, g+8}
                mma_s8_k16(acc[nt], a[2], a[3], bc[2*nt + 1]); // ks1: same rows
            }
            #pragma unroll
            for (int e = 0; e < 8; e++) bc[e] = bn[e];
        }

        // epilogue: dist = ||c||^2 - 2*dot/S^2 ; update per-thread top-3
        #pragma unroll
        for (int nt = 0; nt < 4; nt++) {
            int colb = n0 + nt * 8 + ctg * 2;
            float cn0 = scn[colb], cn1 = scn[colb + 1];
            t3ins(t3d[0], t3i[0], fmaf(QINV2, (float)acc[nt][0], cn0), colb);
            t3ins(t3d[0], t3i[0], fmaf(QINV2, (float)acc[nt][1], cn1), colb + 1);
            t3ins(t3d[1], t3i[1], fmaf(QINV2, (float)acc[nt][2], cn0), colb);
            t3ins(t3d[1], t3i[1], fmaf(QINV2, (float)acc[nt][3], cn1), colb + 1);
        }
    }

    // ---- quad merge (lanes xor 1, xor 2 share the same rows)
    #pragma unroll
    for (int delta = 1; delta <= 2; delta <<= 1) {
        #pragma unroll
        for (int rw = 0; rw < 2; rw++) {
            float od[3]; int oi[3];
            #pragma unroll
            for (int s = 0; s < 3; s++) {
                od[s] = __shfl_xor_sync(0xffffffffu, t3d[rw][s], delta);
                oi[s] = __shfl_xor_sync(0xffffffffu, t3i[rw][s], delta);
            }
            #pragma unroll
            for (int s = 0; s < 3; s++) t3ins(t3d[rw], t3i[rw], od[s], oi[s]);
        }
    }

    // ---- write per-team per-row top-3 to smem
    {
        float* T3D = (float*)(smem + OFF_T3D);
        int*   T3I = (int*)(smem + OFF_T3I);
        if (ctg == 0) {
            #pragma unroll
            for (int rw = 0; rw < 2; rw++) {        // rw = rowhalf
                int r = wm * 16 + rw * 8 + g;
                int base = (team * 64 + r) * 3;
                #pragma unroll
                for (int s = 0; s < 3; s++) { T3D[base + s] = t3d[rw][s]; T3I[base + s] = t3i[rw][s]; }
            }
        }
    }
    __syncthreads();

    // ---- final per-row selection: merge 6 candidates, margin test, fp32 then fp64 rerank
    if (tid < M_CTA) {
        const float* T3D = (const float*)(smem + OFF_T3D);
        const int*   T3I = (const int*)(smem + OFF_T3I);
        float cd[6]; int ci[6];
        #pragma unroll
        for (int s = 0; s < 3; s++) {
            cd[s]     = T3D[tid * 3 + s];          ci[s]     = T3I[tid * 3 + s];
            cd[3 + s] = T3D[(64 + tid) * 3 + s];   ci[3 + s] = T3I[(64 + tid) * 3 + s];
        }
        float d1 = 3.4e38f, d2 = 3.4e38f; int i1 = 0;
        #pragma unroll
        for (int s = 0; s < 6; s++) {
            if (cd[s] < d1) { d2 = d1; d1 = cd[s]; i1 = ci[s]; }
            else if (cd[s] < d2) { d2 = cd[s]; }
        }
        int fi = i1;
        if (!(d2 - d1 > 4.0f)) {
            // fp32 rerank of the 6 candidates
            const float4* zr = (const float4*)(z + (rowBase + tid) * DDIM);
            float bd = 3.4e38f, bd2 = 3.4e38f; int bi = KDICT;
            #pragma unroll 1
            for (int s = 0; s < 6; s++) {
                int ic = ci[s];
                const float4* cp = (const float4*)(cb + (size_t)ic * DDIM);
                float dot = 0.f;
                #pragma unroll 4
                for (int k = 0; k < DDIM / 4; k++) {
                    float4 a = zr[k], b = cp[k];
                    dot = fmaf(a.x, b.x, dot); dot = fmaf(a.y, b.y, dot);
                    dot = fmaf(a.z, b.z, dot); dot = fmaf(a.w, b.w, dot);
                }
                float d = fmaf(-2.f, dot, g_cnorm_f[ic]);
                if (d < bd || (d == bd && ic < bi)) { bd2 = bd; bd = d; bi = ic; }
                else if (d < bd2) bd2 = d;
            }
            fi = bi;
            if (bd2 - bd < 0.05f) {
                // exact fp64 rerank (near-tie)
                const float* zrs = z + (rowBase + tid) * DDIM;
                double best = 1.8e308; fi = KDICT;
                #pragma unroll 1
                for (int s = 0; s < 6; s++) {
                    int ic = ci[s];
                    const float* cp = cb + (size_t)ic * DDIM;
                    double a = 0.0;
                    for (int k = 0; k < DDIM; k++) a += (double)zrs[k] * (double)cp[k];
                    double d = g_cnorm_d[ic] - 2.0 * a;
                    if (d < best || (d == best && ic < fi)) { best = d; fi = ic; }
                }
            }
        }
        ((int*)(smem + OFF_IDX))[tid] = fi;
        atomicAdd(&g_counts[fi], 1.0f);
    }
    __syncthreads();

    // ---- gather z_q = codebook[idx], accumulate sum((z_q - z)^2)
    {
        float part = 0.f;
        const int* sidx = (const int*)(smem + OFF_IDX);
        const float4* cb4 = (const float4*)cb;
        const float4* z4a = (const float4*)z;
        float4* out4 = (float4*)out;
        #pragma unroll 2
        for (int it = 0; it < 16; it++) {
            int i4 = tid + it * 256;
            int row = i4 >> 6, c4 = i4 & 63;
            int id = sidx[row];
            float4 c  = cb4[(size_t)id * (DDIM / 4) + c4];
            float4 zz = z4a[(rowBase + row) * (DDIM / 4) + c4];
            out4[(rowBase + row) * (DDIM / 4) + c4] = c;
            float dx = c.x - zz.x, dy = c.y - zz.y, dz = c.z - zz.z, dw = c.w - zz.w;
            part += dx * dx + dy * dy + dz * dz + dw * dw;
        }
        #pragma unroll
        for (int o = 16; o > 0; o >>= 1) part += __shfl_down_sync(0xffffffffu, part, o);
        if (lane == 0) atomicAdd(&g_loss_sum, part);
    }
}

// ===================== K2: loss + perplexity finalize =====================
__global__ void vq_final(const int* __restrict__ flg, float* __restrict__ out, int zn) {
    __shared__ float red[256];
    int tid = threadIdx.x;
    float local = 0.f;
    float invn = 1.f / (float)(zn / DDIM);
    for (int i = tid; i < KDICT; i += 256) {
        float e = g_counts[i] * invn;
        local += e * logf(e + 1e-10f);
    }
    red[tid] = local;
    __syncthreads();
    for (int o = 128; o > 0; o >>= 1) {
        if (tid < o) red[tid] += red[tid + o];
        __syncthreads();
    }
    if (tid == 0) {
        out[zn + 1] = expf(-red[0]);
        float m = g_loss_sum / (float)zn;
        out[zn] = (*flg) ? (m + 0.001f * m) : 0.f;
    }
}

// ===================== launch =====================
extern "C" void kernel_launch(void* const* d_in, const int* in_sizes, int n_in,
                              void* d_out, int out_size) {
    const float* z  = (const float*)d_in[0];
    const float* cb = (const float*)d_in[1];
    const int* flg  = (const int*)d_in[2];
    float* out = (float*)d_out;
    int zn = in_sizes[0];                       // 16777216
    int rows = zn / DDIM;                       // 65536
    int grid = rows / M_CTA;                    // 1024

    cudaFuncSetAttribute(vq_main, cudaFuncAttributeMaxDynamicSharedMemorySize, SMEM_BYTES);

    vq_prep<<<KDICT / 8, 256>>>(cb);
    vq_main<<<grid, 256, SMEM_BYTES>>>(z, cb, out);
    vq_final<<<1, 256>>>(flg, out, zn);
}

// round 15
// speedup vs baseline: 1.3089x; 1.3089x over previous
#include <cuda_runtime.h>
#include <cstdint>
#include <math.h>

// ===================== problem constants =====================
#define DDIM    256
#define KDICT   1024
#define M_CTA   64
#define N_CHUNK 32
#define N_STAGE 16              // chunks per team (2 teams * 16 * 32 = 1024)
#define NKS     16              // k16 steps over DDIM
#define QSCALE  32.0f
#define QINV2   (-2.0f / (QSCALE * QSCALE))   // -2/1024

// ===================== smem layout (bytes) =====================
#define OFF_A     0
#define A_BYTES   (M_CTA*DDIM)                   // 16384 int8 frag layout
#define OFF_B     16384                          // 4 ping-pong bufs (team,pp) x 8192
#define B_BUF     8192
#define OFF_CN    (OFF_B + 4*B_BUF)              // 49152 : 1024 f32 norms
#define OFF_T3D   (OFF_CN + KDICT*4)             // 53248 : [2][64][3] f32
#define OFF_T3I   (OFF_T3D + 2*64*3*4)           // 54784 : [2][64][3] i32
#define OFF_IDX   (OFF_T3I + 2*64*3*4)           // 56320 : [64] i32
#define SMEM_BYTES (OFF_IDX + 256)               // 56576 (x4 CTA = 226KB/SM)

// ===================== device scratch (no allocs allowed) =====================
__device__ __align__(16) float    g_cnorm_f[KDICT];
__device__ __align__(16) double   g_cnorm_d[KDICT];
// int8 codebook, packed u32, PER-COL PAIRED WORD ORDER:
// word j' = kq*8 + ctg*2 + kh   (from original j = kq*8 + kh*4 + ctg)
__device__ __align__(16) uint32_t g_cb_i8[KDICT * DDIM / 4];
__device__ float g_loss_sum;
__device__ float g_counts[KDICT];

// ===================== helpers =====================
__device__ __forceinline__ uint32_t smem_to_u32(const void* p) {
    uint32_t a;
    asm("{ .reg .u64 t; cvta.to.shared.u64 t, %1; cvt.u32.u64 %0, t; }" : "=r"(a) : "l"(p));
    return a;
}

__device__ __forceinline__ uint32_t quant4(float4 v) {
    int a = __float2int_rn(fminf(fmaxf(v.x * QSCALE, -127.f), 127.f));
    int b = __float2int_rn(fminf(fmaxf(v.y * QSCALE, -127.f), 127.f));
    int c = __float2int_rn(fminf(fmaxf(v.z * QSCALE, -127.f), 127.f));
    int d = __float2int_rn(fminf(fmaxf(v.w * QSCALE, -127.f), 127.f));
    return (uint32_t)(a & 255) | ((uint32_t)(b & 255) << 8)
         | ((uint32_t)(c & 255) << 16) | ((uint32_t)(d & 255) << 24);
}

// m16n8k16 s8: a0 = row g (k=ctg*4..+3), a1 = row g+8. b0 = col g, k = ctg*4..+3.
// c0/c1 = row g cols ctg*2/+1; c2/c3 = row g+8.   (R6-validated)
__device__ __forceinline__ void mma_s8_k16(int d[4], uint32_t a0, uint32_t a1, uint32_t b0) {
    asm volatile(
        "mma.sync.aligned.m16n8k16.row.col.s32.s8.s8.s32 "
        "{%0,%1,%2,%3}, {%4,%5}, {%6}, {%0,%1,%2,%3};"
        : "+r"(d[0]), "+r"(d[1]), "+r"(d[2]), "+r"(d[3])
        : "r"(a0), "r"(a1), "r"(b0));
}

__device__ __forceinline__ void t3ins(float d[3], int idx[3], float nd, int ni) {
    if (nd < d[2]) {
        if (nd < d[1]) {
            d[2] = d[1]; idx[2] = idx[1];
            if (nd < d[0]) { d[1] = d[0]; idx[1] = idx[0]; d[0] = nd; idx[0] = ni; }
            else           { d[1] = nd;  idx[1] = ni; }
        } else { d[2] = nd; idx[2] = ni; }
    }
}

// ===================== K0: codebook norms + permuted int8 codebook + zero accumulators =====================
__global__ void vq_prep(const float* __restrict__ cb) {
    int tid = threadIdx.x;
    if (blockIdx.x == 0) {
        if (tid == 0) g_loss_sum = 0.f;
        for (int i = tid; i < KDICT; i += 256) g_counts[i] = 0.f;
    }
    int row  = blockIdx.x * 8 + (tid >> 5);   // 128 blocks * 8 warps = 1024 rows
    int lane = tid & 31;
    const float4* r4 = (const float4*)(cb + (size_t)row * DDIM);
    double s = 0.0;
    #pragma unroll
    for (int j = lane; j < 64; j += 32) {
        float4 v = __ldg(&r4[j]);
        s += (double)v.x * v.x + (double)v.y * v.y + (double)v.z * v.z + (double)v.w * v.w;
        // paired word order: j = kq*8 + kh*4 + ctg  ->  j' = kq*8 + ctg*2 + kh
        int jp = (j & 0x38) | ((j & 3) << 1) | ((j >> 2) & 1);
        g_cb_i8[row * 64 + jp] = quant4(v);
    }
    #pragma unroll
    for (int o = 16; o > 0; o >>= 1) s += __shfl_down_sync(0xffffffffu, s, o);
    if (lane == 0) { g_cnorm_d[row] = s; g_cnorm_f[row] = (float)s; }
}

// ===================== K1: int8 IMMA GEMM + top-3 argmin + rerank + gather =====================
__global__ __launch_bounds__(256, 4)
void vq_main(const float* __restrict__ z, const float* __restrict__ cb,
             float* __restrict__ out) {
    extern __shared__ char smem[];
    const uint32_t sb  = smem_to_u32(smem);
    const int tid  = threadIdx.x;
    const int team = tid >> 7;          // 0 or 1
    const int tt   = tid & 127;         // thread-in-team
    const int wm   = (tid >> 5) & 3;    // warp m16-block within team
    const int lane = tid & 31;
    const int g    = lane >> 2;
    const int ctg  = lane & 3;
    const size_t rowBase = (size_t)blockIdx.x * M_CTA;

    // ---- codebook norms -> smem (256 thr x float4 = 1024 floats)
    {
        const float4* cf4 = (const float4*)g_cnorm_f;
        *((float4*)(smem + OFF_CN) + tid) = __ldg(&cf4[tid]);
    }

    // B buffer for (team, pp): granule-pair qp (32B) swizzled by col
    //   dst(col n, qp, half) = n*256 + ((qp ^ (n&7))<<5) + (half<<4)
    // src is already in paired word order, so 16B granules copy verbatim.
    const uint32_t bTeam = sb + OFF_B + (uint32_t)(team << 1) * B_BUF;

    // ---- prologue: async-load first int8 B chunk for this team (chunk = team, pp = 0)
    {
        const char* src = (const char*)g_cb_i8 + (size_t)(team * N_CHUNK) * DDIM;
        #pragma unroll
        for (int q = 0; q < 4; q++) {
            int gi   = tt + q * 128;            // 0..511 granules of 16B
            int n    = gi >> 4;
            int gr   = gi & 15;
            int qp   = gr >> 1, half = gr & 1;
            uint32_t dst = bTeam + (uint32_t)(n * 256)
                         + (uint32_t)((qp ^ (n & 7)) << 5) + (uint32_t)(half << 4);
            asm volatile("cp.async.cg.shared.global [%0], [%1], 16;"
                         :: "r"(dst), "l"(src + n * 256 + gr * 16));
        }
        asm volatile("cp.async.commit_group;");
    }

    // ---- prologue: A tile 64x256 fp32 -> int8, m16n8k16 fragment layout.
    // Block per (mw 0..3, kq 0..7): 512 bytes holding BOTH k16 steps (kh 0/1):
    //   word = (mw*8+kq)*128 + (lane' ^ ((kq&7)<<2))*4 + (kh*2 + rowhalf)
    {
        const float4* z4 = (const float4*)z + rowBase * (DDIM / 4);
        uint32_t* A = (uint32_t*)(smem + OFF_A);
        #pragma unroll 4
        for (int it = 0; it < 16; it++) {
            int i4 = tid + it * 256;            // 0..4095
            int r  = i4 >> 6;                   // row 0..63
            int k0 = (i4 & 63) << 2;            // k 0..252, mult of 4
            uint32_t pack = quant4(__ldg(&z4[i4]));
            int mw = r >> 4, rho = r & 15;
            int gg = rho & 7, rh = rho >> 3;
            int ks = k0 >> 4, tg = (k0 & 15) >> 2;
            int kq = ks >> 1, kh = ks & 1;
            int lanep = (gg * 4 + tg) ^ ((kq & 7) << 2);
            int word  = (mw * 8 + kq) * 128 + lanep * 4 + (kh * 2 + rh);
            A[word] = pack;
        }
    }
    __syncthreads();

    // ---- running per-thread top-3 for 2 row-slots (rows g, g+8 of block wm)
    float t3d[2][3]; int t3i[2][3];
    #pragma unroll
    for (int rw = 0; rw < 2; rw++)
        #pragma unroll
        for (int s = 0; s < 3; s++) { t3d[rw][s] = 3.4e38f; t3i[rw][s] = 0; }

    const float* scn = (const float*)(smem + OFF_CN);
    const uint32_t aBase = sb + OFF_A + (uint32_t)(wm << 12);   // wm*4096

    for (int stage = 0; stage < N_STAGE; stage++) {
        const int chunk = stage * 2 + team;
        const int n0 = chunk * N_CHUNK;
        const uint32_t bufB = bTeam + (uint32_t)(stage & 1) * B_BUF;

        asm volatile("cp.async.wait_group 0;" ::: "memory");
        asm volatile("bar.sync %0, 128;" :: "r"(team + 1) : "memory");

        // prefetch next chunk into the OTHER pp buffer (stage-1 readers passed the bar)
        if (stage + 1 < N_STAGE) {
            const char* src = (const char*)g_cb_i8 + (size_t)((chunk + 2) * N_CHUNK) * DDIM;
            const uint32_t dstB = bTeam + (uint32_t)((stage + 1) & 1) * B_BUF;
            #pragma unroll
            for (int q = 0; q < 4; q++) {
                int gi   = tt + q * 128;
                int n    = gi >> 4;
                int gr   = gi & 15;
                int qp   = gr >> 1, half = gr & 1;
                uint32_t dst = dstB + (uint32_t)(n * 256)
                             + (uint32_t)((qp ^ (n & 7)) << 5) + (uint32_t)(half << 4);
                asm volatile("cp.async.cg.shared.global [%0], [%1], 16;"
                             :: "r"(dst), "l"(src + n * 256 + gr * 16));
            }
            asm volatile("cp.async.commit_group;");
        }

        int acc[4][4];
        #pragma unroll
        for (int nt = 0; nt < 4; nt++)
            #pragma unroll
            for (int e = 0; e < 4; e++) acc[nt][e] = 0;

        // per-nt column bases (kq-invariant)
        uint32_t colBase[4];
        #pragma unroll
        for (int nt = 0; nt < 4; nt++) {
            int n = nt * 8 + g;
            colBase[nt] = bufB + (uint32_t)(n << 8) + (uint32_t)(ctg << 3);
        }
        const int nsw = g & 7;   // n&7 == g for all nt

        #pragma unroll
        for (int kq = 0; kq < NKS / 2; kq++) {
            // batch all loads: 1 LDS.128 (a) + 4 LDS.64 (b pairs), then 8 MMAs
            uint32_t a[4];
            uint32_t aAddr = aBase + (uint32_t)(kq << 9)
                           + (uint32_t)((lane ^ ((kq & 7) << 2)) << 4);
            asm volatile("ld.shared.v4.b32 {%0,%1,%2,%3}, [%4];"
                : "=r"(a[0]), "=r"(a[1]), "=r"(a[2]), "=r"(a[3]) : "r"(aAddr));
            uint32_t b[8];
            const uint32_t qoff = (uint32_t)((kq ^ nsw) << 5);
            #pragma unroll
            for (int nt = 0; nt < 4; nt++) {
                asm volatile("ld.shared.v2.b32 {%0,%1}, [%2];"
                    : "=r"(b[2*nt]), "=r"(b[2*nt + 1]) : "r"(colBase[nt] + qoff));
            }
            #pragma unroll
            for (int nt = 0; nt < 4; nt++) {
                mma_s8_k16(acc[nt], a[0], a[1], b[2*nt]);     // ks0: rows wm*16 + {g, g+8}
                mma_s8_k16(acc[nt], a[2], a[3], b[2*nt + 1]); // ks1: same rows
            }
        }

        // epilogue: dist = ||c||^2 - 2*dot/S^2 ; update per-thread top-3
        #pragma unroll
        for (int nt = 0; nt < 4; nt++) {
            int colb = n0 + nt * 8 + ctg * 2;
            float cn0 = scn[colb], cn1 = scn[colb + 1];
            t3ins(t3d[0], t3i[0], fmaf(QINV2, (float)acc[nt][0], cn0), colb);
            t3ins(t3d[0], t3i[0], fmaf(QINV2, (float)acc[nt][1], cn1), colb + 1);
            t3ins(t3d[1], t3i[1], fmaf(QINV2, (float)acc[nt][2], cn0), colb);
            t3ins(t3d[1], t3i[1], fmaf(QINV2, (float)acc[nt][3], cn1), colb + 1);
        }
    }

    // ---- quad merge (lanes xor 1, xor 2 share the same rows)
    #pragma unroll
    for (int delta = 1; delta <= 2; delta <<= 1) {
        #pragma unroll
        for (int rw = 0; rw < 2; rw++) {
            float od[3]; int oi[3];
            #pragma unroll
            for (int s = 0; s < 3; s++) {
                od[s] = __shfl_xor_sync(0xffffffffu, t3d[rw][s], delta);
                oi[s] = __shfl_xor_sync(0xffffffffu, t3i[rw][s], delta);
            }
            #pragma unroll
            for (int s = 0; s < 3; s++) t3ins(t3d[rw], t3i[rw], od[s], oi[s]);
        }
    }

    // ---- write per-team per-row top-3 to smem
    {
        float* T3D = (float*)(smem + OFF_T3D);
        int*   T3I = (int*)(smem + OFF_T3I);
        if (ctg == 0) {
            #pragma unroll
            for (int rw = 0; rw < 2; rw++) {        // rw = rowhalf
                int r = wm * 16 + rw * 8 + g;
                int base = (team * 64 + r) * 3;
                #pragma unroll
                for (int s = 0; s < 3; s++) { T3D[base + s] = t3d[rw][s]; T3I[base + s] = t3i[rw][s]; }
            }
        }
    }
    __syncthreads();

    // ---- final per-row selection: merge 6 candidates, margin test, fp32 then fp64 rerank
    if (tid < M_CTA) {
        const float* T3D = (const float*)(smem + OFF_T3D);
        const int*   T3I = (const int*)(smem + OFF_T3I);
        float cd[6]; int ci[6];
        #pragma unroll
        for (int s = 0; s < 3; s++) {
            cd[s]     = T3D[tid * 3 + s];          ci[s]     = T3I[tid * 3 + s];
            cd[3 + s] = T3D[(64 + tid) * 3 + s];   ci[3 + s] = T3I[(64 + tid) * 3 + s];
        }
        float d1 = 3.4e38f, d2 = 3.4e38f; int i1 = 0;
        #pragma unroll
        for (int s = 0; s < 6; s++) {
            if (cd[s] < d1) { d2 = d1; d1 = cd[s]; i1 = ci[s]; }
            else if (cd[s] < d2) { d2 = cd[s]; }
        }
        int fi = i1;
        if (!(d2 - d1 > 4.0f)) {
            // fp32 rerank of the 6 candidates
            const float4* zr = (const float4*)(z + (rowBase + tid) * DDIM);
            float bd = 3.4e38f, bd2 = 3.4e38f; int bi = KDICT;
            #pragma unroll 1
            for (int s = 0; s < 6; s++) {
                int ic = ci[s];
                const float4* cp = (const float4*)(cb + (size_t)ic * DDIM);
                float dot = 0.f;
                #pragma unroll 4
                for (int k = 0; k < DDIM / 4; k++) {
                    float4 a = zr[k], b = cp[k];
                    dot = fmaf(a.x, b.x, dot); dot = fmaf(a.y, b.y, dot);
                    dot = fmaf(a.z, b.z, dot); dot = fmaf(a.w, b.w, dot);
                }
                float d = fmaf(-2.f, dot, g_cnorm_f[ic]);
                if (d < bd || (d == bd && ic < bi)) { bd2 = bd; bd = d; bi = ic; }
                else if (d < bd2) bd2 = d;
            }
            fi = bi;
            if (bd2 - bd < 0.05f) {
                // exact fp64 rerank (near-tie)
                const float* zrs = z + (rowBase + tid) * DDIM;
                double best = 1.8e308; fi = KDICT;
                #pragma unroll 1
                for (int s = 0; s < 6; s++) {
                    int ic = ci[s];
                    const float* cp = cb + (size_t)ic * DDIM;
                    double a = 0.0;
                    for (int k = 0; k < DDIM; k++) a += (double)zrs[k] * (double)cp[k];
                    double d = g_cnorm_d[ic] - 2.0 * a;
                    if (d < best || (d == best && ic < fi)) { best = d; fi = ic; }
                }
            }
        }
        ((int*)(smem + OFF_IDX))[tid] = fi;
        atomicAdd(&g_counts[fi], 1.0f);
    }
    __syncthreads();

    // ---- gather z_q = codebook[idx], accumulate sum((z_q - z)^2)
    {
        float part = 0.f;
        const int* sidx = (const int*)(smem + OFF_IDX);
        const float4* cb4 = (const float4*)cb;
        const float4* z4a = (const float4*)z;
        float4* out4 = (float4*)out;
        #pragma unroll 2
        for (int it = 0; it < 16; it++) {
            int i4 = tid + it * 256;
            int row = i4 >> 6, c4 = i4 & 63;
            int id = sidx[row];
            float4 c  = cb4[(size_t)id * (DDIM / 4) + c4];
            float4 zz = z4a[(rowBase + row) * (DDIM / 4) + c4];
            out4[(rowBase + row) * (DDIM / 4) + c4] = c;
            float dx = c.x - zz.x, dy = c.y - zz.y, dz = c.z - zz.z, dw = c.w - zz.w;
            part += dx * dx + dy * dy + dz * dz + dw * dw;
        }
        #pragma unroll
        for (int o = 16; o > 0; o >>= 1) part += __shfl_down_sync(0xffffffffu, part, o);
        if (lane == 0) atomicAdd(&g_loss_sum, part);
    }
}

// ===================== K2: loss + perplexity finalize =====================
__global__ void vq_final(const int* __restrict__ flg, float* __restrict__ out, int zn) {
    __shared__ float red[256];
    int tid = threadIdx.x;
    float local = 0.f;
    float invn = 1.f / (float)(zn / DDIM);
    for (int i = tid; i < KDICT; i += 256) {
        float e = g_counts[i] * invn;
        local += e * logf(e + 1e-10f);
    }
    red[tid] = local;
    __syncthreads();
    for (int o = 128; o > 0; o >>= 1) {
        if (tid < o) red[tid] += red[tid + o];
        __syncthreads();
    }
    if (tid == 0) {
        out[zn + 1] = expf(-red[0]);
        float m = g_loss_sum / (float)zn;
        out[zn] = (*flg) ? (m + 0.001f * m) : 0.f;
    }
}

// ===================== launch =====================
extern "C" void kernel_launch(void* const* d_in, const int* in_sizes, int n_in,
                              void* d_out, int out_size) {
    const float* z  = (const float*)d_in[0];
    const float* cb = (const float*)d_in[1];
    const int* flg  = (const int*)d_in[2];
    float* out = (float*)d_out;
    int zn = in_sizes[0];                       // 16777216
    int rows = zn / DDIM;                       // 65536
    int grid = rows / M_CTA;                    // 1024

    cudaFuncSetAttribute(vq_main, cudaFuncAttributeMaxDynamicSharedMemorySize, SMEM_BYTES);

    vq_prep<<<KDICT / 8, 256>>>(cb);
    vq_main<<<grid, 256, SMEM_BYTES>>>(z, cb, out);
    vq_final<<<1, 256>>>(flg, out, zn);
}

// round 16
// speedup vs baseline: 1.3422x; 1.0255x over previous
#include <cuda_runtime.h>
#include <cstdint>
#include <math.h>

// ===================== problem constants =====================
#define DDIM    256
#define KDICT   1024
#define M_CTA   64
#define N_CHUNK 32
#define N_STAGE 16              // chunks per team (2 teams * 16 * 32 = 1024)
#define NKS     16              // k16 steps over DDIM
#define QSCALE  32.0f
#define QINV2   (-2.0f / (QSCALE * QSCALE))   // -2/1024

// ===================== smem layout (bytes) =====================
#define OFF_A     0
#define A_BYTES   (M_CTA*DDIM)                   // 16384 int8 frag layout
#define OFF_B     16384                          // 4 ping-pong bufs (team,pp) x 8192
#define B_BUF     8192
#define OFF_CN    (OFF_B + 4*B_BUF)              // 49152 : 1024 f32 norms
#define OFF_T3D   (OFF_CN + KDICT*4)             // 53248 : [2][64][3] f32
#define OFF_T3I   (OFF_T3D + 2*64*3*4)           // 54784 : [2][64][3] i32
#define OFF_IDX   (OFF_T3I + 2*64*3*4)           // 56320 : [64] i32
#define SMEM_BYTES (OFF_IDX + 256)               // 56576 (x4 CTA = 226KB/SM)

// ===================== device scratch (no allocs allowed) =====================
__device__ __align__(16) float    g_cnorm_f[KDICT];
__device__ __align__(16) double   g_cnorm_d[KDICT];
// int8 codebook, packed u32, PER-COL PAIRED WORD ORDER:
// word j' = kq*8 + ctg*2 + kh   (from original j = kq*8 + kh*4 + ctg)
__device__ __align__(16) uint32_t g_cb_i8[KDICT * DDIM / 4];
__device__ float g_loss_sum;
__device__ float g_counts[KDICT];

// ===================== helpers =====================
__device__ __forceinline__ uint32_t smem_to_u32(const void* p) {
    uint32_t a;
    asm("{ .reg .u64 t; cvta.to.shared.u64 t, %1; cvt.u32.u64 %0, t; }" : "=r"(a) : "l"(p));
    return a;
}

__device__ __forceinline__ uint32_t quant4(float4 v) {
    int a = __float2int_rn(fminf(fmaxf(v.x * QSCALE, -127.f), 127.f));
    int b = __float2int_rn(fminf(fmaxf(v.y * QSCALE, -127.f), 127.f));
    int c = __float2int_rn(fminf(fmaxf(v.z * QSCALE, -127.f), 127.f));
    int d = __float2int_rn(fminf(fmaxf(v.w * QSCALE, -127.f), 127.f));
    return (uint32_t)(a & 255) | ((uint32_t)(b & 255) << 8)
         | ((uint32_t)(c & 255) << 16) | ((uint32_t)(d & 255) << 24);
}

// m16n8k16 s8: a0 = row g (k=ctg*4..+3), a1 = row g+8. b0 = col g, k = ctg*4..+3.
// c0/c1 = row g cols ctg*2/+1; c2/c3 = row g+8.   (R6-validated)
__device__ __forceinline__ void mma_s8_k16(int d[4], uint32_t a0, uint32_t a1, uint32_t b0) {
    asm volatile(
        "mma.sync.aligned.m16n8k16.row.col.s32.s8.s8.s32 "
        "{%0,%1,%2,%3}, {%4,%5}, {%6}, {%0,%1,%2,%3};"
        : "+r"(d[0]), "+r"(d[1]), "+r"(d[2]), "+r"(d[3])
        : "r"(a0), "r"(a1), "r"(b0));
}

__device__ __forceinline__ void t3ins(float d[3], int idx[3], float nd, int ni) {
    if (nd < d[2]) {
        if (nd < d[1]) {
            d[2] = d[1]; idx[2] = idx[1];
            if (nd < d[0]) { d[1] = d[0]; idx[1] = idx[0]; d[0] = nd; idx[0] = ni; }
            else           { d[1] = nd;  idx[1] = ni; }
        } else { d[2] = nd; idx[2] = ni; }
    }
}

// ===================== K0: codebook norms + permuted int8 codebook + zero accumulators =====================
__global__ void vq_prep(const float* __restrict__ cb) {
    int tid = threadIdx.x;
    if (blockIdx.x == 0) {
        if (tid == 0) g_loss_sum = 0.f;
        for (int i = tid; i < KDICT; i += 256) g_counts[i] = 0.f;
    }
    int row  = blockIdx.x * 8 + (tid >> 5);   // 128 blocks * 8 warps = 1024 rows
    int lane = tid & 31;
    const float4* r4 = (const float4*)(cb + (size_t)row * DDIM);
    double s = 0.0;
    #pragma unroll
    for (int j = lane; j < 64; j += 32) {
        float4 v = r4[j];
        s += (double)v.x * v.x + (double)v.y * v.y + (double)v.z * v.z + (double)v.w * v.w;
        // paired word order: j = kq*8 + kh*4 + ctg  ->  j' = kq*8 + ctg*2 + kh
        int jp = (j & 0x38) | ((j & 3) << 1) | ((j >> 2) & 1);
        g_cb_i8[row * 64 + jp] = quant4(v);
    }
    #pragma unroll
    for (int o = 16; o > 0; o >>= 1) s += __shfl_down_sync(0xffffffffu, s, o);
    if (lane == 0) { g_cnorm_d[row] = s; g_cnorm_f[row] = (float)s; }
}

// ===================== K1: int8 IMMA GEMM + top-3 argmin + rerank + gather =====================
__global__ __launch_bounds__(256, 4)
void vq_main(const float* __restrict__ z, const float* __restrict__ cb,
             float* __restrict__ out) {
    extern __shared__ char smem[];
    const uint32_t sb  = smem_to_u32(smem);
    const int tid  = threadIdx.x;
    const int team = tid >> 7;          // 0 or 1
    const int tt   = tid & 127;         // thread-in-team
    const int wm   = (tid >> 5) & 3;    // warp m16-block within team
    const int lane = tid & 31;
    const int g    = lane >> 2;
    const int ctg  = lane & 3;
    const size_t rowBase = (size_t)blockIdx.x * M_CTA;

    // ---- codebook norms -> smem (256 thr x float4 = 1024 floats)
    {
        const float4* cf4 = (const float4*)g_cnorm_f;
        *((float4*)(smem + OFF_CN) + tid) = cf4[tid];
    }

    // B buffer for (team, pp): granule-pair qp (32B) swizzled by col
    //   dst(col n, qp, half) = n*256 + ((qp ^ (n&7))<<5) + (half<<4)
    // src is already in paired word order, so 16B granules copy verbatim.
    const uint32_t bTeam = sb + OFF_B + (uint32_t)(team << 1) * B_BUF;

    // ---- prologue: async-load first int8 B chunk for this team (chunk = team, pp = 0)
    {
        const char* src = (const char*)g_cb_i8 + (size_t)(team * N_CHUNK) * DDIM;
        #pragma unroll
        for (int q = 0; q < 4; q++) {
            int gi   = tt + q * 128;            // 0..511 granules of 16B
            int n    = gi >> 4;
            int gr   = gi & 15;
            int qp   = gr >> 1, half = gr & 1;
            uint32_t dst = bTeam + (uint32_t)(n * 256)
                         + (uint32_t)((qp ^ (n & 7)) << 5) + (uint32_t)(half << 4);
            asm volatile("cp.async.cg.shared.global [%0], [%1], 16;"
                         :: "r"(dst), "l"(src + n * 256 + gr * 16));
        }
        asm volatile("cp.async.commit_group;");
    }

    // ---- prologue: A tile 64x256 fp32 -> int8, m16n8k16 fragment layout.
    // Block per (mw 0..3, kq 0..7): 512 bytes holding BOTH k16 steps (kh 0/1):
    //   word = (mw*8+kq)*128 + (lane' ^ ((kq&7)<<2))*4 + (kh*2 + rowhalf)
    {
        const float4* z4 = (const float4*)z + rowBase * (DDIM / 4);
        uint32_t* A = (uint32_t*)(smem + OFF_A);
        #pragma unroll 4
        for (int it = 0; it < 16; it++) {
            int i4 = tid + it * 256;            // 0..4095
            int r  = i4 >> 6;                   // row 0..63
            int k0 = (i4 & 63) << 2;            // k 0..252, mult of 4
            uint32_t pack = quant4(z4[i4]);
            int mw = r >> 4, rho = r & 15;
            int gg = rho & 7, rh = rho >> 3;
            int ks = k0 >> 4, tg = (k0 & 15) >> 2;
            int kq = ks >> 1, kh = ks & 1;
            int lanep = (gg * 4 + tg) ^ ((kq & 7) << 2);
            int word  = (mw * 8 + kq) * 128 + lanep * 4 + (kh * 2 + rh);
            A[word] = pack;
        }
    }
    __syncthreads();

    // ---- running per-thread top-3 for 2 row-slots (rows g, g+8 of block wm)
    float t3d[2][3]; int t3i[2][3];
    #pragma unroll
    for (int rw = 0; rw < 2; rw++)
        #pragma unroll
        for (int s = 0; s < 3; s++) { t3d[rw][s] = 3.4e38f; t3i[rw][s] = 0; }

    const float* scn = (const float*)(smem + OFF_CN);
    const uint32_t aBase = sb + OFF_A + (uint32_t)(wm << 12);   // wm*4096

    for (int stage = 0; stage < N_STAGE; stage++) {
        const int chunk = stage * 2 + team;
        const int n0 = chunk * N_CHUNK;
        const uint32_t bufB = bTeam + (uint32_t)(stage & 1) * B_BUF;

        asm volatile("cp.async.wait_group 0;" ::: "memory");
        asm volatile("bar.sync %0, 128;" :: "r"(team + 1) : "memory");

        // prefetch next chunk into the OTHER pp buffer (stage-1 readers passed the bar)
        if (stage + 1 < N_STAGE) {
            const char* src = (const char*)g_cb_i8 + (size_t)((chunk + 2) * N_CHUNK) * DDIM;
            const uint32_t dstB = bTeam + (uint32_t)((stage + 1) & 1) * B_BUF;
            #pragma unroll
            for (int q = 0; q < 4; q++) {
                int gi   = tt + q * 128;
                int n    = gi >> 4;
                int gr   = gi & 15;
                int qp   = gr >> 1, half = gr & 1;
                uint32_t dst = dstB + (uint32_t)(n * 256)
                             + (uint32_t)((qp ^ (n & 7)) << 5) + (uint32_t)(half << 4);
                asm volatile("cp.async.cg.shared.global [%0], [%1], 16;"
                             :: "r"(dst), "l"(src + n * 256 + gr * 16));
            }
            asm volatile("cp.async.commit_group;");
        }

        int acc[4][4];
        #pragma unroll
        for (int nt = 0; nt < 4; nt++)
            #pragma unroll
            for (int e = 0; e < 4; e++) acc[nt][e] = 0;

        // per-nt column bases (kq-invariant)
        uint32_t colBase[4];
        #pragma unroll
        for (int nt = 0; nt < 4; nt++) {
            int n = nt * 8 + g;
            colBase[nt] = bufB + (uint32_t)(n << 8) + (uint32_t)(ctg << 3);
        }
        const int nsw = g & 7;   // n&7 == g for all nt

        #pragma unroll 4
        for (int kq = 0; kq < NKS / 2; kq++) {
            // batch all loads: 1 LDS.128 (a) + 4 LDS.64 (b pairs), then 8 MMAs
            uint32_t a[4];
            uint32_t aAddr = aBase + (uint32_t)(kq << 9)
                           + (uint32_t)((lane ^ ((kq & 7) << 2)) << 4);
            asm volatile("ld.shared.v4.b32 {%0,%1,%2,%3}, [%4];"
                : "=r"(a[0]), "=r"(a[1]), "=r"(a[2]), "=r"(a[3]) : "r"(aAddr));
            uint32_t b[8];
            const uint32_t qoff = (uint32_t)((kq ^ nsw) << 5);
            #pragma unroll
            for (int nt = 0; nt < 4; nt++) {
                asm volatile("ld.shared.v2.b32 {%0,%1}, [%2];"
                    : "=r"(b[2*nt]), "=r"(b[2*nt + 1]) : "r"(colBase[nt] + qoff));
            }
            #pragma unroll
            for (int nt = 0; nt < 4; nt++) {
                mma_s8_k16(acc[nt], a[0], a[1], b[2*nt]);     // ks0: rows wm*16 + {g, g+8}
                mma_s8_k16(acc[nt], a[2], a[3], b[2*nt + 1]); // ks1: same rows
            }
        }

        // epilogue: dist = ||c||^2 - 2*dot/S^2 ; update per-thread top-3
        #pragma unroll
        for (int nt = 0; nt < 4; nt++) {
            int colb = n0 + nt * 8 + ctg * 2;
            float cn0 = scn[colb], cn1 = scn[colb + 1];
            t3ins(t3d[0], t3i[0], fmaf(QINV2, (float)acc[nt][0], cn0), colb);
            t3ins(t3d[0], t3i[0], fmaf(QINV2, (float)acc[nt][1], cn1), colb + 1);
            t3ins(t3d[1], t3i[1], fmaf(QINV2, (float)acc[nt][2], cn0), colb);
            t3ins(t3d[1], t3i[1], fmaf(QINV2, (float)acc[nt][3], cn1), colb + 1);
        }
    }

    // ---- quad merge (lanes xor 1, xor 2 share the same rows)
    #pragma unroll
    for (int delta = 1; delta <= 2; delta <<= 1) {
        #pragma unroll
        for (int rw = 0; rw < 2; rw++) {
            float od[3]; int oi[3];
            #pragma unroll
            for (int s = 0; s < 3; s++) {
                od[s] = __shfl_xor_sync(0xffffffffu, t3d[rw][s], delta);
                oi[s] = __shfl_xor_sync(0xffffffffu, t3i[rw][s], delta);
            }
            #pragma unroll
            for (int s = 0; s < 3; s++) t3ins(t3d[rw], t3i[rw], od[s], oi[s]);
        }
    }

    // ---- write per-team per-row top-3 to smem
    {
        float* T3D = (float*)(smem + OFF_T3D);
        int*   T3I = (int*)(smem + OFF_T3I);
        if (ctg == 0) {
            #pragma unroll
            for (int rw = 0; rw < 2; rw++) {        // rw = rowhalf
                int r = wm * 16 + rw * 8 + g;
                int base = (team * 64 + r) * 3;
                #pragma unroll
                for (int s = 0; s < 3; s++) { T3D[base + s] = t3d[rw][s]; T3I[base + s] = t3i[rw][s]; }
            }
        }
    }
    __syncthreads();

    // ---- final per-row selection: merge 6 candidates, margin test, fp32 then fp64 rerank
    if (tid < M_CTA) {
        const float* T3D = (const float*)(smem + OFF_T3D);
        const int*   T3I = (const int*)(smem + OFF_T3I);
        float cd[6]; int ci[6];
        #pragma unroll
        for (int s = 0; s < 3; s++) {
            cd[s]     = T3D[tid * 3 + s];          ci[s]     = T3I[tid * 3 + s];
            cd[3 + s] = T3D[(64 + tid) * 3 + s];   ci[3 + s] = T3I[(64 + tid) * 3 + s];
        }
        float d1 = 3.4e38f, d2 = 3.4e38f; int i1 = 0;
        #pragma unroll
        for (int s = 0; s < 6; s++) {
            if (cd[s] < d1) { d2 = d1; d1 = cd[s]; i1 = ci[s]; }
            else if (cd[s] < d2) { d2 = cd[s]; }
        }
        int fi = i1;
        if (!(d2 - d1 > 4.0f)) {
            // fp32 rerank of the 6 candidates
            const float4* zr = (const float4*)(z + (rowBase + tid) * DDIM);
            float bd = 3.4e38f, bd2 = 3.4e38f; int bi = KDICT;
            #pragma unroll 1
            for (int s = 0; s < 6; s++) {
                int ic = ci[s];
                const float4* cp = (const float4*)(cb + (size_t)ic * DDIM);
                float dot = 0.f;
                #pragma unroll 4
                for (int k = 0; k < DDIM / 4; k++) {
                    float4 a = zr[k], b = cp[k];
                    dot = fmaf(a.x, b.x, dot); dot = fmaf(a.y, b.y, dot);
                    dot = fmaf(a.z, b.z, dot); dot = fmaf(a.w, b.w, dot);
                }
                float d = fmaf(-2.f, dot, g_cnorm_f[ic]);
                if (d < bd || (d == bd && ic < bi)) { bd2 = bd; bd = d; bi = ic; }
                else if (d < bd2) bd2 = d;
            }
            fi = bi;
            if (bd2 - bd < 0.05f) {
                // exact fp64 rerank (near-tie)
                const float* zrs = z + (rowBase + tid) * DDIM;
                double best = 1.8e308; fi = KDICT;
                #pragma unroll 1
                for (int s = 0; s < 6; s++) {
                    int ic = ci[s];
                    const float* cp = cb + (size_t)ic * DDIM;
                    double a = 0.0;
                    for (int k = 0; k < DDIM; k++) a += (double)zrs[k] * (double)cp[k];
                    double d = g_cnorm_d[ic] - 2.0 * a;
                    if (d < best || (d == best && ic < fi)) { best = d; fi = ic; }
                }
            }
        }
        ((int*)(smem + OFF_IDX))[tid] = fi;
        atomicAdd(&g_counts[fi], 1.0f);
    }
    __syncthreads();

    // ---- gather z_q = codebook[idx], accumulate sum((z_q - z)^2)
    {
        float part = 0.f;
        const int* sidx = (const int*)(smem + OFF_IDX);
        const float4* cb4 = (const float4*)cb;
        const float4* z4a = (const float4*)z;
        float4* out4 = (float4*)out;
        #pragma unroll 2
        for (int it = 0; it < 16; it++) {
            int i4 = tid + it * 256;
            int row = i4 >> 6, c4 = i4 & 63;
            int id = sidx[row];
            float4 c  = cb4[(size_t)id * (DDIM / 4) + c4];
            float4 zz = z4a[(rowBase + row) * (DDIM / 4) + c4];
            out4[(rowBase + row) * (DDIM / 4) + c4] = c;
            float dx = c.x - zz.x, dy = c.y - zz.y, dz = c.z - zz.z, dw = c.w - zz.w;
            part += dx * dx + dy * dy + dz * dz + dw * dw;
        }
        #pragma unroll
        for (int o = 16; o > 0; o >>= 1) part += __shfl_down_sync(0xffffffffu, part, o);
        if (lane == 0) atomicAdd(&g_loss_sum, part);
    }
}

// ===================== K2: loss + perplexity finalize =====================
__global__ void vq_final(const int* __restrict__ flg, float* __restrict__ out, int zn) {
    __shared__ float red[256];
    int tid = threadIdx.x;
    float local = 0.f;
    float invn = 1.f / (float)(zn / DDIM);
    for (int i = tid; i < KDICT; i += 256) {
        float e = g_counts[i] * invn;
        local += e * logf(e + 1e-10f);
    }
    red[tid] = local;
    __syncthreads();
    for (int o = 128; o > 0; o >>= 1) {
        if (tid < o) red[tid] += red[tid + o];
        __syncthreads();
    }
    if (tid == 0) {
        out[zn + 1] = expf(-red[0]);
        float m = g_loss_sum / (float)zn;
        out[zn] = (*flg) ? (m + 0.001f * m) : 0.f;
    }
}

// ===================== launch =====================
extern "C" void kernel_launch(void* const* d_in, const int* in_sizes, int n_in,
                              void* d_out, int out_size) {
    const float* z  = (const float*)d_in[0];
    const float* cb = (const float*)d_in[1];
    const int* flg  = (const int*)d_in[2];
    float* out = (float*)d_out;
    int zn = in_sizes[0];                       // 16777216
    int rows = zn / DDIM;                       // 65536
    int grid = rows / M_CTA;                    // 1024

    cudaFuncSetAttribute(vq_main, cudaFuncAttributeMaxDynamicSharedMemorySize, SMEM_BYTES);

    vq_prep<<<KDICT / 8, 256>>>(cb);
    vq_main<<<grid, 256, SMEM_BYTES>>>(z, cb, out);
    vq_final<<<1, 256>>>(flg, out, zn);
}